// round 3
// baseline (speedup 1.0000x reference)
#include <cuda_runtime.h>

#define NODES  8448
#define NB     10
#define ITERS  5
#define TPB    768
#define NPT    11            // 768 * 11 = 8448
#define NBATCH 1024
#define RPC    4             // batch rows per CTA (packed as float4)
#define NGROUPS (NBATCH / RPC)   // 256

// smem: float4 tanh buffer (135168) + float2 prev for rows 0..1 (67584)
#define SMEM_BYTES (NODES * 16 + NODES * 8)   // 202752

// Global scratch (static __device__ arrays; no allocation).
__device__ unsigned int g_pk[5][NODES];        // u16 neighbor ids, packed 2-per-u32, SoA
__device__ float4       g_wllr[NGROUPS][NODES];
__device__ float2       g_P2[NGROUPS][NODES];  // prev vm rows 2..3

// ---------------------------------------------------------------------------
__global__ void prep_idx_kernel(const int* __restrict__ check_idx)
{
    int k = blockIdx.x * blockDim.x + threadIdx.x;
    if (k < NODES * 5) {
        int n = k / 5, j = k % 5;
        unsigned a = (unsigned)check_idx[n * NB + 2 * j];
        unsigned b = (unsigned)check_idx[n * NB + 2 * j + 1];
        g_pk[j][n] = (a & 0xFFFFu) | (b << 16);
    }
}

// tanh(clip(0.5*v, -9.9, 9.9)) = 1 - 2/(1 + e^{clip(v, -19.8, 19.8)})
__device__ __forceinline__ float fast_tanh_half(float v)
{
    float x = fminf(19.8f, fmaxf(-19.8f, v));
    float e = __expf(x);                  // ex2-based, rel err ~3e-6
    float r = __frcp_rn(1.0f + e);
    return fmaf(-2.0f, r, 1.0f);
}

__device__ __forceinline__ float fast_2atanh(float p)
{
    p = fminf(0.999999f, fmaxf(-0.999999f, p));
    return __logf(__fdividef(1.0f + p, 1.0f - p));
}

__device__ __forceinline__ float fast_sigmoid(float z)
{
    return __frcp_rn(1.0f + __expf(-z));
}

// ---------------------------------------------------------------------------
__global__ __launch_bounds__(TPB, 1)
void ldpc4_kernel(const float* __restrict__ input_llr,
                  const float* __restrict__ w_ch,
                  const float* __restrict__ w_res,   // (2, NODES)
                  float*       __restrict__ out)
{
    extern __shared__ unsigned char smem_raw[];
    float4* st    = reinterpret_cast<float4*>(smem_raw);            // tanh, 4 rows
    float2* sprev = reinterpret_cast<float2*>(smem_raw + NODES*16); // prev rows 0..1

    const int tid  = threadIdx.x;
    const int g    = blockIdx.x;
    const int row0 = g * RPC;
    const float* llr0 = input_llr + (size_t)row0 * NODES;

    float4 cur[NPT];   // current var_messages (4 batch rows per node)

    #pragma unroll
    for (int i = 0; i < NPT; i++) {
        const int n = tid + i * TPB;
        const float wc = w_ch[n];
        float4 wl;
        wl.x = llr0[n]             * wc;
        wl.y = llr0[NODES + n]     * wc;
        wl.z = llr0[2 * NODES + n] * wc;
        wl.w = llr0[3 * NODES + n] * wc;
        g_wllr[g][n] = wl;
        cur[i] = wl;
    }

    for (int it = 0; it < ITERS; it++) {
        // Phase A: publish t = tanh(clip(0.5*vm)) for 4 rows (one LDS.128 store).
        #pragma unroll
        for (int i = 0; i < NPT; i++) {
            const int n = tid + i * TPB;
            const float4 v = cur[i];
            float4 t;
            t.x = fast_tanh_half(v.x);
            t.y = fast_tanh_half(v.y);
            t.z = fast_tanh_half(v.z);
            t.w = fast_tanh_half(v.w);
            st[n] = t;
        }
        __syncthreads();

        // Phase B: gather 10 neighbors (LDS.128 serves 4 rows), product,
        // 2*atanh, residual, update.
        #pragma unroll 2
        for (int i = 0; i < NPT; i++) {
            const int n = tid + i * TPB;
            // two accumulators to shorten the FMUL dependency chain
            float4 p0 = make_float4(1.f, 1.f, 1.f, 1.f);
            float4 p1 = make_float4(1.f, 1.f, 1.f, 1.f);
            #pragma unroll
            for (int j = 0; j < 5; j++) {
                const unsigned pk = g_pk[j][n];
                const float4 a = st[pk & 0xFFFFu];
                const float4 b = st[pk >> 16];
                p0.x *= a.x; p0.y *= a.y; p0.z *= a.z; p0.w *= a.w;
                p1.x *= b.x; p1.y *= b.y; p1.z *= b.z; p1.w *= b.w;
            }
            float4 p;
            p.x = p0.x * p1.x;  p.y = p0.y * p1.y;
            p.z = p0.z * p1.z;  p.w = p0.w * p1.w;

            float4 cm;
            cm.x = fast_2atanh(p.x);
            cm.y = fast_2atanh(p.y);
            cm.z = fast_2atanh(p.z);
            cm.w = fast_2atanh(p.w);

            const float w0 = w_res[n];
            const float w1 = w_res[NODES + n];
            float2 prA = make_float2(0.f, 0.f);   // rows 0..1
            float2 prB = make_float2(0.f, 0.f);   // rows 2..3
            if (it > 0) { prA = sprev[n]; prB = g_P2[g][n]; }

            const float4 c = cur[i];
            sprev[n]   = make_float2(c.x, c.y);   // becomes prev next iter
            g_P2[g][n] = make_float2(c.z, c.w);

            const float4 wl = g_wllr[g][n];
            float4 nv;
            nv.x = wl.x + cm.x + w0 * c.x + w1 * prA.x;
            nv.y = wl.y + cm.y + w0 * c.y + w1 * prA.y;
            nv.z = wl.z + cm.z + w0 * c.z + w1 * prB.x;
            nv.w = wl.w + cm.w + w0 * c.w + w1 * prB.y;
            cur[i] = nv;
        }
        __syncthreads();   // protect st before next iteration's Phase A
    }

    // Epilogue: soft_bits = sigmoid(vm + input_llr)
    #pragma unroll
    for (int i = 0; i < NPT; i++) {
        const int n = tid + i * TPB;
        const float4 c = cur[i];
        float* o = out + (size_t)row0 * NODES;
        o[n]             = fast_sigmoid(c.x + llr0[n]);
        o[NODES + n]     = fast_sigmoid(c.y + llr0[NODES + n]);
        o[2 * NODES + n] = fast_sigmoid(c.z + llr0[2 * NODES + n]);
        o[3 * NODES + n] = fast_sigmoid(c.w + llr0[3 * NODES + n]);
    }
}

// ---------------------------------------------------------------------------
extern "C" void kernel_launch(void* const* d_in, const int* in_sizes, int n_in,
                              void* d_out, int out_size)
{
    const float* input_llr = (const float*)d_in[0];
    const float* w_ch      = (const float*)d_in[1];
    const float* w_res     = (const float*)d_in[2];
    const int*   check_idx = (const int*)d_in[3];
    // d_in[4] (var_index_tensor) is unused by the reference computation.
    float* out = (float*)d_out;

    prep_idx_kernel<<<(NODES * 5 + 255) / 256, 256>>>(check_idx);

    cudaFuncSetAttribute(ldpc4_kernel,
                         cudaFuncAttributeMaxDynamicSharedMemorySize, SMEM_BYTES);
    ldpc4_kernel<<<NGROUPS, TPB, SMEM_BYTES>>>(input_llr, w_ch, w_res, out);
}